// round 4
// baseline (speedup 1.0000x reference)
#include <cuda_runtime.h>
#include <cuda_bf16.h>
#include <cstdint>

#define NN      50000
#define NE      800000
#define NRELS   200

// -------- scratch (device globals; allocation is forbidden) --------
__device__ int          g_cnt[NN];          // dst degree (re-zeroed by k_agg each call)
__device__ int          g_off[NN];          // exclusive offsets; advanced to "end" by scatter
__device__ unsigned int g_key[NE];          // (src | etype<<16) sorted by dst
__device__ float        g_relB[NRELS * 64]; // rel @ (W1+W4)
__device__ float        g_A[NN * 64];       // (Σ h)/cnt
__device__ float        g_B[NN * 64];       // (Σ h⊙r)/cnt
__device__ float        g_C[NN * 64];       // (Σ relB)/cnt

// -------- f32x2 helpers --------
#define FMA2(acc, a, b) \
    asm("fma.rn.f32x2 %0, %1, %2, %0;" : "+l"(acc) : "l"(a), "l"(b))
#define PACK_DUP(h2, h) \
    asm("mov.b64 %0, {%1, %1};" : "=l"(h2) : "f"(h))
#define UNPACK2(lo, hi, v) \
    asm("mov.b64 {%0, %1}, %2;" : "=f"(lo), "=f"(hi) : "l"(v))

// -------- K1: relB[t][j] = sum_k rel[t][k] * (W1[k][j] + W4[k][j]) --------
__global__ void k_relB(const float* __restrict__ rel, const float* __restrict__ Wn) {
    int t = blockIdx.x;
    int j = threadIdx.x;
    float s = 0.0f;
    #pragma unroll 8
    for (int k = 0; k < 64; k++)
        s += rel[t * 64 + k] * (Wn[k * 64 + j] + Wn[(192 + k) * 64 + j]);
    g_relB[t * 64 + j] = s;
}

// -------- K2: dst degree histogram (g_cnt pre-zeroed by prior k_agg / init) --------
__global__ void k_deg(const int* __restrict__ dst, int E) {
    int i = blockIdx.x * blockDim.x + threadIdx.x;
    int stride = gridDim.x * blockDim.x;
    int n4 = E >> 2;
    const int4* d4 = (const int4*)dst;
    for (int j = i; j < n4; j += stride) {
        int4 v = d4[j];
        atomicAdd(&g_cnt[v.x], 1);
        atomicAdd(&g_cnt[v.y], 1);
        atomicAdd(&g_cnt[v.z], 1);
        atomicAdd(&g_cnt[v.w], 1);
    }
    if (i < (E & 3)) atomicAdd(&g_cnt[dst[(n4 << 2) + i]], 1);
}

// -------- K3: single-block exclusive scan of g_cnt -> g_off --------
#define SCHUNK 49
__global__ __launch_bounds__(1024) void k_scan() {
    __shared__ int wsum[32];
    int tid = threadIdx.x;
    int lane = tid & 31, wid = tid >> 5;
    int base = tid * SCHUNK;
    int lim = min(base + SCHUNK, NN);
    int s = 0;
    for (int j = base; j < lim; j++) s += g_cnt[j];
    int x = s;
    #pragma unroll
    for (int d = 1; d < 32; d <<= 1) {
        int y = __shfl_up_sync(0xffffffffu, x, d);
        if (lane >= d) x += y;
    }
    if (lane == 31) wsum[wid] = x;
    __syncthreads();
    if (wid == 0) {
        int y = wsum[lane];
        int z = y;
        #pragma unroll
        for (int d = 1; d < 32; d <<= 1) {
            int t = __shfl_up_sync(0xffffffffu, z, d);
            if (lane >= d) z += t;
        }
        wsum[lane] = z - y;   // exclusive warp offset
    }
    __syncthreads();
    int run = (x - s) + wsum[wid];
    for (int j = base; j < lim; j++) {
        int c = g_cnt[j];
        g_off[j] = run;
        run += c;
    }
}

// -------- K4: counting-sort scatter by dst (atomics advance g_off to segment end) --------
__global__ void k_scatter(const int* __restrict__ src, const int* __restrict__ dst,
                          const int* __restrict__ et, int E) {
    int i = blockIdx.x * blockDim.x + threadIdx.x;
    int stride = gridDim.x * blockDim.x;
    int n4 = E >> 2;
    const int4* s4 = (const int4*)src;
    const int4* d4 = (const int4*)dst;
    const int4* t4 = (const int4*)et;
    for (int j = i; j < n4; j += stride) {
        int4 s = s4[j];
        int4 d = d4[j];
        int4 t = t4[j];
        int p0 = atomicAdd(&g_off[d.x], 1);
        int p1 = atomicAdd(&g_off[d.y], 1);
        int p2 = atomicAdd(&g_off[d.z], 1);
        int p3 = atomicAdd(&g_off[d.w], 1);
        g_key[p0] = (unsigned)s.x | ((unsigned)t.x << 16);
        g_key[p1] = (unsigned)s.y | ((unsigned)t.y << 16);
        g_key[p2] = (unsigned)s.z | ((unsigned)t.z << 16);
        g_key[p3] = (unsigned)s.w | ((unsigned)t.w << 16);
    }
    if (i < (E & 3)) {
        int e = (n4 << 2) + i;
        int p = atomicAdd(&g_off[dst[e]], 1);
        g_key[p] = (unsigned)src[e] | ((unsigned)et[e] << 16);
    }
}

// -------- K5: per-dst aggregation: one warp/node, float4 lanes, 2 edges/iter --------
__global__ __launch_bounds__(256) void k_agg(const float* __restrict__ feat,
                                             const float* __restrict__ rel) {
    int w = (blockIdx.x * 256 + threadIdx.x) >> 5;
    if (w >= NN) return;
    int lane = threadIdx.x & 31;
    // after scatter, g_off[j] == original exclusive end of segment j
    int beg = w ? g_off[w - 1] : 0;
    int end = g_off[w];
    if (lane == 0) g_cnt[w] = 0;     // re-zero for next call (deterministic)

    int half = lane >> 4;            // 0: even edges, 1: odd edges
    int l16 = lane & 15;

    const float4* f4  = (const float4*)feat;
    const float4* r4  = (const float4*)rel;
    const float4* rb4 = (const float4*)g_relB;

    float4 a = make_float4(0.f, 0.f, 0.f, 0.f);
    float4 b = a, c = a;

    #pragma unroll 2
    for (int i = beg + half; i < end; i += 2) {
        unsigned int k = g_key[i];
        int s = (int)(k & 0xFFFFu);
        int t = (int)(k >> 16);
        float4 h  = f4[s * 16 + l16];
        float4 r  = r4[t * 16 + l16];
        float4 rb = rb4[t * 16 + l16];
        a.x += h.x; a.y += h.y; a.z += h.z; a.w += h.w;
        b.x = fmaf(h.x, r.x, b.x); b.y = fmaf(h.y, r.y, b.y);
        b.z = fmaf(h.z, r.z, b.z); b.w = fmaf(h.w, r.w, b.w);
        c.x += rb.x; c.y += rb.y; c.z += rb.z; c.w += rb.w;
    }

    // combine the two half-warp partial sums
    #define RED16(f) f += __shfl_xor_sync(0xffffffffu, f, 16)
    RED16(a.x); RED16(a.y); RED16(a.z); RED16(a.w);
    RED16(b.x); RED16(b.y); RED16(b.z); RED16(b.w);
    RED16(c.x); RED16(c.y); RED16(c.z); RED16(c.w);
    #undef RED16

    float inv = 1.0f / fmaxf((float)(end - beg), 1.0f);
    if (lane < 16) {
        ((float4*)g_A)[w * 16 + l16] = make_float4(a.x * inv, a.y * inv, a.z * inv, a.w * inv);
        ((float4*)g_C)[w * 16 + l16] = make_float4(c.x * inv, c.y * inv, c.z * inv, c.w * inv);
    } else {
        ((float4*)g_B)[w * 16 + l16] = make_float4(b.x * inv, b.y * inv, b.z * inv, b.w * inv);
    }
}

// -------- K6: out = A@W13 + B@W2 + C + feat@LW  (64 nodes / block, 512 thr) --------
#define TS 65
#define FNODES 64
#define FSMEM ((3 * 4096 + 3 * FNODES * TS) * 4)

__global__ __launch_bounds__(512) void k_final(const float* __restrict__ feat,
                                               const float* __restrict__ Wn,
                                               const float* __restrict__ LW,
                                               float* __restrict__ out, int N) {
    extern __shared__ float smem[];
    float* W13s = smem;                 // 4096
    float* W2s  = smem + 4096;          // 4096
    float* LWs  = smem + 8192;          // 4096
    float* As   = smem + 12288;         // 64*65
    float* Bs   = As + FNODES * TS;
    float* Fs   = Bs + FNODES * TS;

    int tid = threadIdx.x;
    for (int idx = tid; idx < 4096; idx += 512) {
        W13s[idx] = Wn[idx] + Wn[8192 + idx];
        W2s[idx]  = Wn[4096 + idx];
        LWs[idx]  = LW[idx];
    }

    int n0 = blockIdx.x * FNODES;
    // 3 matrices x 64 rows x 16 float4 = 3072 slots
    #pragma unroll
    for (int p = 0; p < 6; p++) {
        int idx = p * 512 + tid;
        int mat = idx >> 10;
        int slot = idx & 1023;
        int e = slot >> 4, c4 = slot & 15;
        int node = n0 + e;
        const float* srcp = (mat == 0) ? g_A : (mat == 1) ? g_B : feat;
        float* dstp = (mat == 0) ? As : (mat == 1) ? Bs : Fs;
        float4 v = make_float4(0.f, 0.f, 0.f, 0.f);
        if (node < N) v = *(const float4*)&srcp[(size_t)node * 64 + c4 * 4];
        float* hp = &dstp[e * TS + c4 * 4];
        hp[0] = v.x; hp[1] = v.y; hp[2] = v.z; hp[3] = v.w;
    }
    __syncthreads();

    int ty = tid >> 3, tx = tid & 7, jj = tx * 8;
    int node = n0 + ty;

    unsigned long long a0 = 0, a1 = 0, a2 = 0, a3 = 0;
    #pragma unroll 4
    for (int k = 0; k < 64; k++) {
        float la = As[ty * TS + k];
        float lb = Bs[ty * TS + k];
        float lf = Fs[ty * TS + k];
        unsigned long long la2, lb2, lf2;
        PACK_DUP(la2, la); PACK_DUP(lb2, lb); PACK_DUP(lf2, lf);

        const float* w13 = &W13s[(k << 6) + jj];
        const float* w2  = &W2s[(k << 6) + jj];
        const float* lw  = &LWs[(k << 6) + jj];
        ulonglong2 wA = *reinterpret_cast<const ulonglong2*>(w13);
        ulonglong2 wB = *reinterpret_cast<const ulonglong2*>(w13 + 4);
        ulonglong2 vA = *reinterpret_cast<const ulonglong2*>(w2);
        ulonglong2 vB = *reinterpret_cast<const ulonglong2*>(w2 + 4);
        ulonglong2 uA = *reinterpret_cast<const ulonglong2*>(lw);
        ulonglong2 uB = *reinterpret_cast<const ulonglong2*>(lw + 4);

        FMA2(a0, la2, wA.x); FMA2(a1, la2, wA.y); FMA2(a2, la2, wB.x); FMA2(a3, la2, wB.y);
        FMA2(a0, lb2, vA.x); FMA2(a1, lb2, vA.y); FMA2(a2, lb2, vB.x); FMA2(a3, lb2, vB.y);
        FMA2(a0, lf2, uA.x); FMA2(a1, lf2, uA.y); FMA2(a2, lf2, uB.x); FMA2(a3, lf2, uB.y);
    }

    if (node < N) {
        float4 c0 = *(const float4*)&g_C[(size_t)node * 64 + jj];
        float4 c1 = *(const float4*)&g_C[(size_t)node * 64 + jj + 4];
        float v0, v1, v2, v3, v4, v5, v6, v7;
        UNPACK2(v0, v1, a0); UNPACK2(v2, v3, a1);
        UNPACK2(v4, v5, a2); UNPACK2(v6, v7, a3);
        float* p = out + (size_t)node * 64 + jj;
        *(float4*)p       = make_float4(v0 + c0.x, v1 + c0.y, v2 + c0.z, v3 + c0.w);
        *(float4*)(p + 4) = make_float4(v4 + c1.x, v5 + c1.y, v6 + c1.z, v7 + c1.w);
    }
}

// -------- launch --------
extern "C" void kernel_launch(void* const* d_in, const int* in_sizes, int n_in,
                              void* d_out, int out_size) {
    const float* feat = (const float*)d_in[0];
    const float* rel  = (const float*)d_in[1];
    const float* Wn   = (const float*)d_in[2];
    const float* LW   = (const float*)d_in[3];
    const int*   src  = (const int*)d_in[4];
    const int*   dst  = (const int*)d_in[5];
    const int*   et   = (const int*)d_in[6];
    float* out = (float*)d_out;

    int E = in_sizes[4];
    int N = in_sizes[0] / 64;

    cudaFuncSetAttribute(k_final, cudaFuncAttributeMaxDynamicSharedMemorySize, FSMEM);

    k_relB<<<NRELS, 64>>>(rel, Wn);
    k_deg<<<512, 256>>>(dst, E);
    k_scan<<<1, 1024>>>();
    k_scatter<<<800, 256>>>(src, dst, et, E);
    k_agg<<<(NN * 32 + 255) / 256, 256>>>(feat, rel);
    k_final<<<(N + FNODES - 1) / FNODES, 512, FSMEM>>>(feat, Wn, LW, out, N);
}